// round 17
// baseline (speedup 1.0000x reference)
#include <cuda_runtime.h>
#include <cuda_fp16.h>
#include <cstdint>

#define SQ 4096
#define EE 512
#define HH 8
#define DD 64
#define HSZ (SQ*DD)
#define TOT (SQ*EE)

// ------------------- global scratch -------------------
__device__ float g_vf[TOT];   // reused as fp16 buffer for V projection output
__device__ __half g_Qh[TOT], g_Kh[TOT], g_Vh[TOT];
__device__ __half g_W1h[EE*EE], g_W2h[EE*EE], g_W3h[EE*EE];
__device__ __half g_qh[TOT], g_kh[TOT], g_oh[TOT];

// ------------------- helpers -------------------
__device__ __forceinline__ uint32_t smem_u32(const void* p) {
    uint32_t a;
    asm("{ .reg .u64 t; cvta.to.shared.u64 t, %1; cvt.u32.u64 %0, t; }" : "=r"(a) : "l"(p));
    return a;
}
#define LDSM4(R0,R1,R2,R3,ADDR) \
    asm volatile("ldmatrix.sync.aligned.m8n8.x4.shared.b16 {%0,%1,%2,%3}, [%4];" \
        : "=r"(R0),"=r"(R1),"=r"(R2),"=r"(R3) : "r"(ADDR))
#define LDSM4T(R0,R1,R2,R3,ADDR) \
    asm volatile("ldmatrix.sync.aligned.m8n8.x4.trans.shared.b16 {%0,%1,%2,%3}, [%4];" \
        : "=r"(R0),"=r"(R1),"=r"(R2),"=r"(R3) : "r"(ADDR))
#define MMA16816(C,A,B) \
    asm volatile("mma.sync.aligned.m16n8k16.row.col.f32.f16.f16.f32 " \
        "{%0,%1,%2,%3},{%4,%5,%6,%7},{%8,%9},{%0,%1,%2,%3};" \
        : "+f"((C)[0]),"+f"((C)[1]),"+f"((C)[2]),"+f"((C)[3]) \
        : "r"((A)[0]),"r"((A)[1]),"r"((A)[2]),"r"((A)[3]),"r"((B)[0]),"r"((B)[1]))
#define MMA16816H(C0,C1,A,B) \
    asm volatile("mma.sync.aligned.m16n8k16.row.col.f16.f16.f16.f16 " \
        "{%0,%1},{%2,%3,%4,%5},{%6,%7},{%0,%1};" \
        : "+r"(C0),"+r"(C1) \
        : "r"((A)[0]),"r"((A)[1]),"r"((A)[2]),"r"((A)[3]),"r"((B)[0]),"r"((B)[1]))
#define CPA16(DST,SRC) \
    asm volatile("cp.async.cg.shared.global [%0], [%1], 16;" :: "r"(DST), "l"(SRC) : "memory")
#define CPC() asm volatile("cp.async.commit_group;" ::: "memory")
#define CPW(N) asm volatile("cp.async.wait_group %0;" :: "n"(N) : "memory")
#define EX2H2(D) asm("ex2.approx.f16x2 %0, %0;" : "+r"(D))

// ------------------- fp32 -> fp16 convert (3 tensors / launch) --------------
__global__ void cvt1x3(const float4* __restrict__ x0, uint2* __restrict__ h0,
                       const float4* __restrict__ x1, uint2* __restrict__ h1,
                       const float4* __restrict__ x2, uint2* __restrict__ h2) {
    const float4* x = blockIdx.y == 0 ? x0 : blockIdx.y == 1 ? x1 : x2;
    uint2* hi = blockIdx.y == 0 ? h0 : blockIdx.y == 1 ? h1 : h2;
    int i = blockIdx.x * blockDim.x + threadIdx.x;
    float4 v = x[i];
    __half2 a01 = __floats2half2_rn(v.x, v.y);
    __half2 a23 = __floats2half2_rn(v.z, v.w);
    uint2 hv;
    hv.x = *(uint32_t*)&a01; hv.y = *(uint32_t*)&a23;
    hi[i] = hv;
}

// ------------------- fp16 GEMM (K-chunk 16, 4-stage, race-free) --------------
#define GP16 48
#define GMSZ (128*GP16)                  // 6144 B / matrix
#define GSTG (2*GMSZ)                    // 12288 B / stage (A, W)
#define G_SMEM (4*GSTG)                  // 49152 B

struct GemmArgs {
    const __half *Ah[3], *Wh[3];
    const float* bias[3];
    float* Cf[3];
    __half *Ch[3];
    float scale[3];
    int mode[3];   // 0: fp32 out, 2: fp16 out
};

__device__ __forceinline__ void gemm_pf(
    uint32_t sbs, int tid, int m0, int n0, int ch,
    const __half* Ah, const __half* Wh)
{
#pragma unroll
    for (int q = 0; q < 2; q++) {
        int id = q * 256 + tid;
        int mat = id >> 8, rem = id & 255, row = rem >> 1, col = rem & 1;
        const __half* g = (mat == 0 ? Ah : Wh)
            + (size_t)((mat == 0 ? m0 : n0) + row) * EE + ch * 16 + col * 8;
        CPA16(sbs + mat * GMSZ + row * GP16 + col * 16, g);
    }
}

__global__ void __launch_bounds__(256, 2) gemm_mma(GemmArgs ga)
{
    extern __shared__ char sm[];
    uint32_t sb = smem_u32(sm);
    int tid = threadIdx.x, wid = tid >> 5, lane = tid & 31;
    int wm = wid & 3, wn = wid >> 2;
    int m0 = blockIdx.y * 128, n0 = blockIdx.x * 128;
    int z = blockIdx.z;
    int l15 = lane & 15, lh = lane >> 4;

    const __half *Ah = ga.Ah[z], *Wh = ga.Wh[z];
    const float* bias = ga.bias[z];
    float* Cf = ga.Cf[z];
    __half* Chi = ga.Ch[z];
    float scale = ga.scale[z];
    int mode = ga.mode[z];

    float acc[2][8][4] = {};

    gemm_pf(sb,            tid, m0, n0, 0, Ah, Wh); CPC();
    gemm_pf(sb + GSTG,     tid, m0, n0, 1, Ah, Wh); CPC();
    gemm_pf(sb + 2 * GSTG, tid, m0, n0, 2, Ah, Wh); CPC();

    for (int ch = 0; ch < 32; ch++) {
        CPW(2);
        __syncthreads();
        if (ch + 3 < 32)
            gemm_pf(sb + ((ch + 3) & 3) * GSTG, tid, m0, n0, ch + 3, Ah, Wh);
        CPC();
        uint32_t sbs = sb + (ch & 3) * GSTG;

        uint32_t ah[2][4];
#pragma unroll
        for (int mt = 0; mt < 2; mt++) {
            uint32_t addr = sbs + (wm * 32 + mt * 16 + l15) * GP16 + lh * 16;
            LDSM4(ah[mt][0], ah[mt][1], ah[mt][2], ah[mt][3], addr);
        }
#pragma unroll
        for (int jt = 0; jt < 4; jt++) {
            uint32_t addr = sbs + GMSZ + (wn * 64 + jt * 16 + l15) * GP16 + lh * 16;
            uint32_t h0, h1, h2, h3;
            LDSM4(h0, h1, h2, h3, addr);
            uint32_t b0[2] = {h0, h2}, b1[2] = {h1, h3};
#pragma unroll
            for (int mt = 0; mt < 2; mt++) {
                MMA16816(acc[mt][2*jt],   ah[mt], b0);
                MMA16816(acc[mt][2*jt+1], ah[mt], b1);
            }
        }
    }

    int r = lane >> 2, c2 = (lane & 3) * 2;
#pragma unroll
    for (int mt = 0; mt < 2; mt++) {
        size_t rbase = (size_t)(m0 + wm * 32 + mt * 16 + r) * EE + n0 + wn * 64;
#pragma unroll
        for (int j = 0; j < 8; j++) {
            float b0 = __ldg(bias + n0 + wn * 64 + j * 8 + c2);
            float b1 = __ldg(bias + n0 + wn * 64 + j * 8 + c2 + 1);
            float y00 = (acc[mt][j][0] + b0) * scale, y01 = (acc[mt][j][1] + b1) * scale;
            float y10 = (acc[mt][j][2] + b0) * scale, y11 = (acc[mt][j][3] + b1) * scale;
            if (mode == 0) {
                *(float2*)(Cf + rbase + j * 8 + c2)          = make_float2(y00, y01);
                *(float2*)(Cf + rbase + 8 * EE + j * 8 + c2) = make_float2(y10, y11);
            } else {
                __half2 p0 = __floats2half2_rn(y00, y01);
                __half2 p1 = __floats2half2_rn(y10, y11);
                *(uint32_t*)(Chi + rbase + j * 8 + c2)          = *(uint32_t*)&p0;
                *(uint32_t*)(Chi + rbase + 8 * EE + j * 8 + c2) = *(uint32_t*)&p1;
            }
        }
    }
}

// --- fp16 flash attention (KV-chunk 128, 3-stage, trans-V, rowsum-MMA) -------
#define AP16 144
#define AMSZ (128*AP16)                  // 18432 B / matrix (128 kv rows)
#define ASTG (2*AMSZ)                    // 36864 B / stage (K, V)
#define A_SMEM (3*ASTG)                  // 110592 B  (2 CTAs = 221184 < 228KB)

__device__ __forceinline__ void attn_pf(
    uint32_t sbs, int tid, size_t hb, int t0,
    const __half* kh, const __half* vh)
{
#pragma unroll
    for (int q = 0; q < 16; q++) {
        int id = q * 128 + tid;
        int mat = id >> 10, rem = id & 1023, row = rem >> 3, col = rem & 7;
        const __half* g = (mat == 0 ? kh : vh) + hb + (size_t)(t0 + row) * DD + col * 8;
        CPA16(sbs + mat * AMSZ + row * AP16 + col * 16, g);
    }
}

__global__ void __launch_bounds__(128, 2) attn_mma(
    const __half* __restrict__ qh_g, const __half* __restrict__ kh_g,
    const __half* __restrict__ vh_g, __half* __restrict__ oh_g)
{
    extern __shared__ char sm[];
    uint32_t sb = smem_u32(sm);
    int tid = threadIdx.x, wid = tid >> 5, lane = tid & 31;
    int head = blockIdx.y, m0 = blockIdx.x * 128;
    const size_t hb = (size_t)head * HSZ;
    int r = lane >> 2, c2 = (lane & 3) * 2;
    int l15 = lane & 15, lh = lane >> 4;
    // trans-ldmatrix addressing for V (row-major [kv][d])
    int g8 = lane >> 3, w8 = lane & 7;
    int vro = ((g8 >> 1) & 1) * 8 + w8;   // kv within slab
    int vco = (g8 & 1) * 8;               // d octet within jt tile

    attn_pf(sb,        tid, hb, 0,   kh_g, vh_g); CPC();
    attn_pf(sb + ASTG, tid, hb, 128, kh_g, vh_g); CPC();

    // Q fragments: 2 m-tiles of 16 rows (warp covers 32 rows); pre-scaled by 0.125*log2e
    uint32_t qh[2][4][4];
    {
        const __half* q0h = qh_g + hb + (size_t)(m0 + wid * 32) * DD;
#pragma unroll
        for (int mt = 0; mt < 2; mt++)
#pragma unroll
            for (int ks = 0; ks < 4; ks++)
#pragma unroll
                for (int j = 0; j < 4; j++) {
                    int rr = mt * 16 + r + (j & 1) * 8;
                    int kk = ks * 16 + c2 + (j >> 1) * 8;
                    qh[mt][ks][j] = *(const uint32_t*)(q0h + rr * DD + kk);
                }
    }

    float oacc[2][8][4] = {};
    float racc[2][4] = {};
    const uint32_t bones[2] = {0x3C003C00u, 0x3C003C00u};  // fp16 1.0 x2

    for (int t = 0; t < 32; t++) {
        // committed before wait: 2 + t. Need group t done -> pending <= 1.
        CPW(1);
        __syncthreads();   // visibility of chunk t; stage (t+2)%3 reads (from iter t-1) done
        if (t + 2 < 32)
            attn_pf(sb + ((t + 2) % 3) * ASTG, tid, hb, (t + 2) * 128, kh_g, vh_g);
        CPC();             // always commit to keep group counting uniform
        uint32_t sbs = sb + (t % 3) * ASTG;

        // per 16-kv slab: S (f16 accum == P A-frag) -> exp in place -> rowsum MMA + PV
#pragma unroll
        for (int tt = 0; tt < 8; tt++) {
            uint32_t pa[2][4] = {{0u,0u,0u,0u},{0u,0u,0u,0u}};
#pragma unroll
            for (int ks = 0; ks < 4; ks++) {
                uint32_t addr = sbs + (tt * 16 + l15) * AP16 + (ks * 16 + 8 * lh) * 2;
                uint32_t h0, h1, h2, h3;
                LDSM4(h0, h1, h2, h3, addr);
                uint32_t b0[2] = {h0, h2}, b1[2] = {h1, h3};
                MMA16816H(pa[0][0], pa[0][1], qh[0][ks], b0);
                MMA16816H(pa[1][0], pa[1][1], qh[1][ks], b0);
                MMA16816H(pa[0][2], pa[0][3], qh[0][ks], b1);
                MMA16816H(pa[1][2], pa[1][3], qh[1][ks], b1);
            }
            EX2H2(pa[0][0]); EX2H2(pa[0][1]); EX2H2(pa[0][2]); EX2H2(pa[0][3]);
            EX2H2(pa[1][0]); EX2H2(pa[1][1]); EX2H2(pa[1][2]); EX2H2(pa[1][3]);
            MMA16816(racc[0], pa[0], bones);   // exact fp32 rowsum
            MMA16816(racc[1], pa[1], bones);
#pragma unroll
            for (int jt = 0; jt < 4; jt++) {
                uint32_t addr = sbs + AMSZ + (tt * 16 + vro) * AP16 + (jt * 16 + vco) * 2;
                uint32_t h0, h1, h2, h3;
                LDSM4T(h0, h1, h2, h3, addr);
                uint32_t b0[2] = {h0, h2}, b1[2] = {h1, h3};
                MMA16816(oacc[0][2*jt],   pa[0], b0);
                MMA16816(oacc[1][2*jt],   pa[1], b0);
                MMA16816(oacc[0][2*jt+1], pa[0], b1);
                MMA16816(oacc[1][2*jt+1], pa[1], b1);
            }
        }
    }

    // normalize + store (racc[mt][0]=rowsum rows r; [2]=rows r+8)
#pragma unroll
    for (int mt = 0; mt < 2; mt++) {
        float i0 = 1.f / racc[mt][0], i1 = 1.f / racc[mt][2];
        size_t rbase = hb + (size_t)(m0 + wid * 32 + mt * 16 + r) * DD;
#pragma unroll
        for (int j = 0; j < 8; j++) {
            __half2 p0 = __floats2half2_rn(oacc[mt][j][0] * i0, oacc[mt][j][1] * i0);
            __half2 p1 = __floats2half2_rn(oacc[mt][j][2] * i1, oacc[mt][j][3] * i1);
            *(uint32_t*)(oh_g + rbase + j * 8 + c2)          = *(uint32_t*)&p0;
            *(uint32_t*)(oh_g + rbase + 8 * DD + j * 8 + c2) = *(uint32_t*)&p1;
        }
    }
}

// ------------------- host -------------------
extern "C" void kernel_launch(void* const* d_in, const int* in_sizes, int n_in,
                              void* d_out, int out_size) {
    const float* Q    = (const float*)d_in[0];
    const float* K    = (const float*)d_in[1];
    const float* V    = (const float*)d_in[2];
    const float* Wqk  = (const float*)d_in[3];
    const float* bqk  = (const float*)d_in[4];
    const float* Wv   = (const float*)d_in[5];
    const float* bv   = (const float*)d_in[6];
    const float* Wout = (const float*)d_in[7];
    const float* bout = (const float*)d_in[8];
    float* out = (float*)d_out;

    float* vf;
    __half *Qh,*Kh,*Vh,*W1h,*W2h,*W3h,*qh,*kh,*oh;
    cudaGetSymbolAddress((void**)&vf, g_vf);
    cudaGetSymbolAddress((void**)&Qh, g_Qh);   cudaGetSymbolAddress((void**)&Kh, g_Kh);
    cudaGetSymbolAddress((void**)&Vh, g_Vh);
    cudaGetSymbolAddress((void**)&W1h, g_W1h); cudaGetSymbolAddress((void**)&W2h, g_W2h);
    cudaGetSymbolAddress((void**)&W3h, g_W3h);
    cudaGetSymbolAddress((void**)&qh, g_qh);   cudaGetSymbolAddress((void**)&kh, g_kh);
    cudaGetSymbolAddress((void**)&oh, g_oh);
    __half* vf16 = (__half*)vf;

    cudaFuncSetAttribute(gemm_mma, cudaFuncAttributeMaxDynamicSharedMemorySize, G_SMEM);
    cudaFuncSetAttribute(attn_mma, cudaFuncAttributeMaxDynamicSharedMemorySize, A_SMEM);

    const int TB = 256;
    cvt1x3<<<dim3(TOT/4/TB, 3), TB>>>((const float4*)Q, (uint2*)Qh,
                                      (const float4*)K, (uint2*)Kh,
                                      (const float4*)V, (uint2*)Vh);
    cvt1x3<<<dim3(EE*EE/4/TB, 3), TB>>>((const float4*)Wqk,  (uint2*)W1h,
                                        (const float4*)Wv,   (uint2*)W2h,
                                        (const float4*)Wout, (uint2*)W3h);

    const float QSC = 0.125f * 1.4426950408889634f;
    GemmArgs gp = {};
    gp.Ah[0]=Qh; gp.Wh[0]=W1h; gp.bias[0]=bqk; gp.Ch[0]=qh;   gp.scale[0]=QSC; gp.mode[0]=2;
    gp.Ah[1]=Kh; gp.Wh[1]=W1h; gp.bias[1]=bqk; gp.Ch[1]=kh;   gp.scale[1]=1.f; gp.mode[1]=2;
    gp.Ah[2]=Vh; gp.Wh[2]=W2h; gp.bias[2]=bv;  gp.Ch[2]=vf16; gp.scale[2]=1.f; gp.mode[2]=2;
    gemm_mma<<<dim3(EE/128, SQ/128, 3), TB, G_SMEM>>>(gp);

    attn_mma<<<dim3(SQ/128, HH), 128, A_SMEM>>>(qh, kh, vf16, oh);

    GemmArgs go = {};
    go.Ah[0]=oh; go.Wh[0]=W3h; go.bias[0]=bout; go.Cf[0]=out; go.scale[0]=1.f; go.mode[0]=0;
    gemm_mma<<<dim3(EE/128, SQ/128, 1), TB, G_SMEM>>>(go);
}